// round 9
// baseline (speedup 1.0000x reference)
#include <cuda_runtime.h>
#include <cstdint>

// B=256 batches of N=512 x 512 binary (0/1) float32 adjacency.
constexpr int B   = 256;
constexpr int N   = 512;
constexpr int W   = N / 32;    // 16 packed words per row
constexpr int F4  = N / 4;     // 128 float4 per row
constexpr int RPC1 = 32;       // rows per CTA, pack kernel
constexpr int GRID1 = B * (N / RPC1);  // 4096
constexpr int RPC2 = 64;       // rows per CTA, scale kernel
constexpr int GRID2 = B * (N / RPC2);  // 2048

// Scratch (__device__ globals: allocation-free rule).
// Slot layout (transposed): word (c*4+grp) of a row is stored at slot (grp*4+c),
// so group grp's 4 words are one aligned uint4 at index grp.
__device__ unsigned g_bits[(size_t)B * N * W];  // 8 MB (stays L2-resident)
__device__ float    g_dis [(size_t)B * N];      // 512 KB

// ---------------------------------------------------------------------------
// K1: pack + degree. 8 warps x 4 rows (2 front-batched at a time) = 32 rows.
// nib built with exact FFMA arithmetic (entries are 0.0/1.0).
// ---------------------------------------------------------------------------
__global__ void __launch_bounds__(256, 5)
pack_kernel(const float* __restrict__ adj) {
    const int bid   = blockIdx.x;
    const int batch = bid >> 4;
    const int r0    = (bid & 15) * RPC1;

    const int tid  = threadIdx.x;
    const int wid  = tid >> 5;
    const int lane = tid & 31;
    const int sub  = lane & 7;
    const int grp  = lane >> 3;

    const float4* a4 = reinterpret_cast<const float4*>(adj)
                     + ((size_t)batch * N + r0 + wid * 4) * F4;

    #pragma unroll
    for (int k = 0; k < 2; k++) {
        // Front-batch 2 rows = 8 independent LDG.128.
        float4 v[2][4];
        #pragma unroll
        for (int r = 0; r < 2; r++)
            #pragma unroll
            for (int c = 0; c < 4; c++)
                v[r][c] = __ldcs(&a4[(size_t)(2 * k + r) * F4 + c * 32 + lane]);

        #pragma unroll
        for (int r = 0; r < 2; r++) {
            unsigned wreg[4];
            int cnt = 0;
            #pragma unroll
            for (int c = 0; c < 4; c++) {
                // Entries are exactly 0.0/1.0 -> nib is exact in fp32.
                float nf = fmaf(2.0f, v[r][c].y, v[r][c].x);
                nf = fmaf(4.0f, v[r][c].z, nf);
                nf = fmaf(8.0f, v[r][c].w, nf);
                unsigned w = ((unsigned)nf) << (sub * 4);
                w |= __shfl_xor_sync(0xffffffffu, w, 1);
                w |= __shfl_xor_sync(0xffffffffu, w, 2);
                w |= __shfl_xor_sync(0xffffffffu, w, 4);  // all 8 lanes: word c*4+grp
                wreg[c] = w;
                cnt += __popc(w);
            }
            cnt += __shfl_xor_sync(0xffffffffu, cnt, 8);
            cnt += __shfl_xor_sync(0xffffffffu, cnt, 16);

            const int ig = r0 + wid * 4 + 2 * k + r;       // row index within batch
            const int dw = ig >> 5, db = ig & 31;
            const unsigned diagw = __shfl_sync(0xffffffffu, wreg[dw >> 2], (dw & 3) * 8);
            const int diag = (diagw >> db) & 1;
            const int mask = (cnt != 0) ? 1 : 0;           // atom_mask
            const int deg  = cnt - diag + mask;            // degree_hat
            if (grp == (dw & 3) && diag != mask) wreg[dw >> 2] ^= (1u << db);

            if (sub == 0) {                                // 4 lanes emit 64B/row
                uint4 pk = make_uint4(wreg[0], wreg[1], wreg[2], wreg[3]);
                reinterpret_cast<uint4*>(g_bits)[((size_t)batch * N + ig) * 4 + grp] = pk;
            }
            if (lane == 0)
                g_dis[(size_t)batch * N + ig] = (deg > 0) ? rsqrtf((float)deg) : 0.0f;
        }
    }
}

// ---------------------------------------------------------------------------
// K2: out[i][j] = dis[i]*dis[j]*bit(i,j). No smem, no barriers (proven at the
// LTS cap in R8 — unchanged). 8 warps x 8 rows = 64 rows/CTA.
// ---------------------------------------------------------------------------
__global__ void __launch_bounds__(256)
scale_kernel(float* __restrict__ out) {
    const int bid   = blockIdx.x;
    const int batch = bid >> 3;
    const int r0    = (bid & 7) * RPC2;

    const int tid  = threadIdx.x;
    const int wid  = tid >> 5;
    const int lane = tid & 31;
    const int sub  = lane & 7;
    const int grp  = lane >> 3;

    const int lr = r0 + wid * 8;   // first of 8 rows for this warp (within batch)

    // Row-invariant column scales: dreg[c] = dis[c*128 + lane*4 .. +3] (L1/L2-hot).
    const float4* d4 = reinterpret_cast<const float4*>(g_dis + (size_t)batch * N);
    float4 dreg[4];
    #pragma unroll
    for (int c = 0; c < 4; c++) dreg[c] = __ldg(&d4[c * 32 + lane]);

    // Front-batch the 8 rows' packed words (one aligned uint4 per lane-group,
    // L2-resident) and the 8 row scales.
    const uint4* b4 = reinterpret_cast<const uint4*>(g_bits)
                    + ((size_t)batch * N + lr) * 4;
    uint4 wb[8];
    #pragma unroll
    for (int r = 0; r < 8; r++) wb[r] = __ldcg(&b4[(size_t)r * 4 + grp]);

    float di[8];
    #pragma unroll
    for (int r = 0; r < 8; r++) di[r] = __ldg(&g_dis[(size_t)batch * N + lr + r]);

    float4* o4 = reinterpret_cast<float4*>(out) + ((size_t)batch * N + lr) * F4;

    #pragma unroll
    for (int r = 0; r < 8; r++) {
        float4* q = o4 + (size_t)r * F4;
        const unsigned wc[4] = {wb[r].x, wb[r].y, wb[r].z, wb[r].w};  // word c*4+grp
        #pragma unroll
        for (int c = 0; c < 4; c++) {
            const unsigned nib = (wc[c] >> (sub * 4)) & 0xFu;
            const float4 d = dreg[c];
            float4 o;
            o.x = (nib & 1u) ? di[r] * d.x : 0.0f;
            o.y = (nib & 2u) ? di[r] * d.y : 0.0f;
            o.z = (nib & 4u) ? di[r] * d.z : 0.0f;
            o.w = (nib & 8u) ? di[r] * d.w : 0.0f;
            __stcs(&q[c * 32 + lane], o);  // coalesced STG.128 stream
        }
    }
}

extern "C" void kernel_launch(void* const* d_in, const int* in_sizes, int n_in,
                              void* d_out, int out_size) {
    const float* adj = (const float*)d_in[0];
    float* out = (float*)d_out;
    (void)in_sizes; (void)n_in; (void)out_size;

    pack_kernel<<<GRID1, 256>>>(adj);
    scale_kernel<<<GRID2, 256>>>(out);
}

// round 10
// speedup vs baseline: 1.0204x; 1.0204x over previous
#include <cuda_runtime.h>
#include <cstdint>

// B=256 batches of N=512 x 512 binary (0/1) float32 adjacency.
constexpr int B   = 256;
constexpr int N   = 512;
constexpr int W   = N / 32;    // 16 packed words per row
constexpr int F4  = N / 4;     // 128 float4 per row
constexpr int RPC1 = 32;       // rows per CTA, pack kernel
constexpr int GRID1 = B * (N / RPC1);  // 4096
constexpr int RPC2 = 64;       // rows per CTA, scale kernel
constexpr int GRID2 = B * (N / RPC2);  // 2048

// Scratch (__device__ globals: allocation-free rule).
// Transposed slot layout: slot (grp*4+c) of a row holds word (c*4+grp), so the
// uint4 at slot-index grp = words {grp, 4+grp, 8+grp, 12+grp} (what K2 wants).
__device__ unsigned g_bits[(size_t)B * N * W];  // 8 MB (L2-resident)
__device__ float    g_dis [(size_t)B * N];      // 512 KB

// ---------------------------------------------------------------------------
// K1: one warp per row, ballot packing (no dependent shfl chains).
// 8 warps x 4 rows = 32 rows/CTA; 2 rows front-batched (32 scalar LDG).
// ---------------------------------------------------------------------------
__device__ __forceinline__ void pack_row(const float* __restrict__ x /*unused*/) {}

__global__ void __launch_bounds__(256)
pack_kernel(const float* __restrict__ adj) {
    const int bid   = blockIdx.x;
    const int batch = bid >> 4;
    const int r0    = (bid & 15) * RPC1;

    const int tid  = threadIdx.x;
    const int wid  = tid >> 5;
    const int lane = tid & 31;
    const int l16  = lane & 15;

    const float* base = adj + ((size_t)batch * N + r0 + wid * 4) * N;

    #pragma unroll
    for (int k = 0; k < 2; k++) {
        const float* p0 = base + (size_t)(2 * k)     * N;
        const float* p1 = base + (size_t)(2 * k + 1) * N;

        // Front-batch 2 rows = 32 independent coalesced LDG.32 (128B/wavefront).
        float a[W], b[W];
        #pragma unroll
        for (int t = 0; t < W; t++) {
            a[t] = __ldcs(&p0[t * 32 + lane]);
            b[t] = __ldcs(&p1[t * 32 + lane]);
        }

        #pragma unroll
        for (int r = 0; r < 2; r++) {
            const float* x = (r == 0) ? a : b;
            const int ig = r0 + wid * 4 + 2 * k + r;   // row index within batch

            // 16 independent ballots; lane l keeps word l (l<16; 16..31 mirror).
            unsigned myw = 0;
            #pragma unroll
            for (int t = 0; t < W; t++) {
                unsigned bt = __ballot_sync(0xffffffffu, x[t] != 0.0f);
                if (l16 == t) myw = bt;
            }

            // Degree: popc of own word, xor-reduce over the 16-lane group.
            int cnt = __popc(myw);
            cnt += __shfl_xor_sync(0xffffffffu, cnt, 1);
            cnt += __shfl_xor_sync(0xffffffffu, cnt, 2);
            cnt += __shfl_xor_sync(0xffffffffu, cnt, 4);
            cnt += __shfl_xor_sync(0xffffffffu, cnt, 8);

            const int dw = ig >> 5, db = ig & 31;
            const unsigned diagw = __shfl_sync(0xffffffffu, myw, dw);
            const int diag = (diagw >> db) & 1;
            const int mask = (cnt != 0) ? 1 : 0;       // atom_mask
            const int deg  = cnt - diag + mask;        // degree_hat
            if (diag != mask && l16 == dw) myw ^= (1u << db);

            // Transposed-slot store: word l -> slot (l&3)*4 + (l>>2).
            if (lane < 16)
                g_bits[((size_t)batch * N + ig) * W + (lane & 3) * 4 + (lane >> 2)] = myw;
            if (lane == 0)
                g_dis[(size_t)batch * N + ig] = (deg > 0) ? rsqrtf((float)deg) : 0.0f;
        }
    }
}

// ---------------------------------------------------------------------------
// K2: out[i][j] = dis[i]*dis[j]*bit(i,j). No smem, no barriers (proven at the
// LTS cap — unchanged from R8/R9). 8 warps x 8 rows = 64 rows/CTA. PDL entry.
// ---------------------------------------------------------------------------
__global__ void __launch_bounds__(256)
scale_kernel(float* __restrict__ out) {
    const int bid   = blockIdx.x;
    const int batch = bid >> 3;
    const int r0    = (bid & 7) * RPC2;

    const int tid  = threadIdx.x;
    const int wid  = tid >> 5;
    const int lane = tid & 31;
    const int sub  = lane & 7;
    const int grp  = lane >> 3;

    const int lr = r0 + wid * 8;   // first of 8 rows for this warp (within batch)

    // PDL: wait until pack_kernel's writes are visible, then proceed.
    cudaGridDependencySynchronize();

    // Row-invariant column scales: dreg[c] = dis[c*128 + lane*4 .. +3].
    const float4* d4 = reinterpret_cast<const float4*>(g_dis + (size_t)batch * N);
    float4 dreg[4];
    #pragma unroll
    for (int c = 0; c < 4; c++) dreg[c] = __ldg(&d4[c * 32 + lane]);

    // Front-batch the 8 rows' packed words (one aligned uint4 per lane-group,
    // L2-resident) and the 8 row scales.
    const uint4* b4 = reinterpret_cast<const uint4*>(g_bits)
                    + ((size_t)batch * N + lr) * 4;
    uint4 wb[8];
    #pragma unroll
    for (int r = 0; r < 8; r++) wb[r] = __ldcg(&b4[(size_t)r * 4 + grp]);

    float di[8];
    #pragma unroll
    for (int r = 0; r < 8; r++) di[r] = __ldg(&g_dis[(size_t)batch * N + lr + r]);

    float4* o4 = reinterpret_cast<float4*>(out) + ((size_t)batch * N + lr) * F4;

    #pragma unroll
    for (int r = 0; r < 8; r++) {
        float4* q = o4 + (size_t)r * F4;
        const unsigned wc[4] = {wb[r].x, wb[r].y, wb[r].z, wb[r].w};  // word c*4+grp
        #pragma unroll
        for (int c = 0; c < 4; c++) {
            const unsigned nib = (wc[c] >> (sub * 4)) & 0xFu;
            const float4 d = dreg[c];
            float4 o;
            o.x = (nib & 1u) ? di[r] * d.x : 0.0f;
            o.y = (nib & 2u) ? di[r] * d.y : 0.0f;
            o.z = (nib & 4u) ? di[r] * d.z : 0.0f;
            o.w = (nib & 8u) ? di[r] * d.w : 0.0f;
            __stcs(&q[c * 32 + lane], o);  // coalesced STG.128 stream
        }
    }
}

extern "C" void kernel_launch(void* const* d_in, const int* in_sizes, int n_in,
                              void* d_out, int out_size) {
    const float* adj = (const float*)d_in[0];
    float* out = (float*)d_out;
    (void)in_sizes; (void)n_in; (void)out_size;

    pack_kernel<<<GRID1, 256>>>(adj);

    // PDL launch: K2 CTAs may spin up during K1's tail wave; memory dependency
    // is enforced by cudaGridDependencySynchronize() in scale_kernel (implicit
    // completion trigger at K1 end).
    cudaLaunchConfig_t cfg = {};
    cfg.gridDim  = dim3(GRID2);
    cfg.blockDim = dim3(256);
    cudaLaunchAttribute attr[1];
    attr[0].id = cudaLaunchAttributeProgrammaticStreamSerialization;
    attr[0].val.programmaticStreamSerializationAllowed = 1;
    cfg.attrs = attr;
    cfg.numAttrs = 1;
    cudaLaunchKernelEx(&cfg, scale_kernel, out);
}